// round 2
// baseline (speedup 1.0000x reference)
#include <cuda_runtime.h>
#include <cuda_bf16.h>

#define BB 4
#define NN 4096
#define DD 256

// scratch for projected_val = val @ Wv  (16.8 MB)
__device__ float g_pv[BB * NN * DD];

// ---------------------------------------------------------------------------
// Kernel 1: pv[b,n,e] = sum_d val[b,n,d] * Wv[d,e]
// 64 rows per block, full 256 cols, BK=32. 256 threads, 4x16 micro-tile.
// ---------------------------------------------------------------------------
__global__ __launch_bounds__(256) void proj_kernel(const float* __restrict__ val,
                                                   const float* __restrict__ Wv) {
    __shared__ float As[32][65];    // [k][r], 65-stride -> conflict-free
    __shared__ float Ws[32][257];   // [k][c]
    const int t    = threadIdx.x;
    const int row0 = blockIdx.x * 64;
    const int rg   = t >> 4;   // 0..15 -> rows rg*4..rg*4+3
    const int cg   = t & 15;   // 0..15 -> cols cg + 16*j

    float acc[4][16];
#pragma unroll
    for (int i = 0; i < 4; i++)
#pragma unroll
        for (int j = 0; j < 16; j++) acc[i][j] = 0.f;

    for (int kk = 0; kk < DD; kk += 32) {
        // load A chunk transposed As[kc][r]
        {
            const int kc = t & 31;
            const int rb = t >> 5;
#pragma unroll
            for (int i = 0; i < 8; i++) {
                const int r = rb + i * 8;
                As[kc][r] = val[(row0 + r) * DD + kk + kc];
            }
        }
        // load W chunk Ws[k][c]
#pragma unroll 8
        for (int i = 0; i < 32; i++) Ws[i][t] = Wv[(kk + i) * DD + t];
        __syncthreads();

#pragma unroll 4
        for (int k = 0; k < 32; k++) {
            const float a0 = As[k][rg * 4 + 0];
            const float a1 = As[k][rg * 4 + 1];
            const float a2 = As[k][rg * 4 + 2];
            const float a3 = As[k][rg * 4 + 3];
#pragma unroll
            for (int j = 0; j < 16; j++) {
                const float w = Ws[k][cg + 16 * j];
                acc[0][j] += a0 * w;
                acc[1][j] += a1 * w;
                acc[2][j] += a2 * w;
                acc[3][j] += a3 * w;
            }
        }
        __syncthreads();
    }
#pragma unroll
    for (int i = 0; i < 4; i++)
#pragma unroll
        for (int j = 0; j < 16; j++)
            g_pv[(row0 + rg * 4 + i) * DD + cg + 16 * j] = acc[i][j];
}

// ---------------------------------------------------------------------------
// Kernel 2: fused propagation (flash-attention style, softsign edges)
// Per block: 64 query rows of one batch. Loop over 64 key tiles of 64 rows.
//   S[64,64] = Q . K^T   (fp32, 4x4 micro-tile, 16x16 thread grid)
//   P = S / (1 + |S|)    -> smem
//   O[64,256] += P @ Vtile ; ds[64] += P @ state_tile
// ---------------------------------------------------------------------------
__global__ __launch_bounds__(256, 2) void prop_kernel(const float* __restrict__ val,
                                                      const float* __restrict__ state,
                                                      float* __restrict__ out_ds,
                                                      float* __restrict__ out_dv) {
    extern __shared__ float sm[];
    float* Qs      = sm;                 // [256][65]  k-major: Qs[d*65 + r]
    float* Ks      = Qs + 256 * 65;      // [32][65]   Ks[kc*65 + m]
    float* Ps      = Ks + 32 * 65;       // [64][65]   Ps[r*65 + m]
    float* Vs      = Ps + 64 * 65;       // [64][65]   Vs[m*65 + c]
    float* state_s = Vs + 64 * 65;       // [64]

    const int t  = threadIdx.x;
    const int b  = blockIdx.x >> 6;             // 64 row-tiles per batch
    const int n0 = (blockIdx.x & 63) * 64;
    const float* valb = val + (size_t)b * NN * DD;
    const float* pvb  = g_pv + (size_t)b * NN * DD;

    // load Q transposed: Qs[d][r]  (coalesced global, conflict-free smem)
#pragma unroll 8
    for (int i = 0; i < 64; i++) Qs[t * 65 + i] = valb[(n0 + i) * DD + t];

    const int ty = t >> 4, tx = t & 15;  // S-phase mapping
    const int r  = t >> 2, q  = t & 3;   // O-phase mapping

    float o[64];
#pragma unroll
    for (int j = 0; j < 64; j++) o[j] = 0.f;
    float ds = 0.f;

    for (int mt = 0; mt < NN / 64; mt++) {
        const int m0 = mt * 64;
        float s[4][4];
#pragma unroll
        for (int i = 0; i < 4; i++)
#pragma unroll
            for (int j = 0; j < 4; j++) s[i][j] = 0.f;

        for (int kk = 0; kk < DD; kk += 32) {
            __syncthreads();   // protect Ks reuse (+ covers Q load on 1st iter)
            {
                const int kc = t & 31;
                const int mb = t >> 5;
#pragma unroll
                for (int i = 0; i < 8; i++) {
                    const int m = mb + i * 8;
                    Ks[kc * 65 + m] = valb[(m0 + m) * DD + kk + kc];
                }
            }
            if (kk == 0 && t < 64) state_s[t] = state[b * NN + m0 + t];
            __syncthreads();

#pragma unroll 8
            for (int kc = 0; kc < 32; kc++) {
                const int d = kk + kc;
                float qv[4], kv[4];
#pragma unroll
                for (int i = 0; i < 4; i++) qv[i] = Qs[d * 65 + ty * 4 + i];
#pragma unroll
                for (int j = 0; j < 4; j++) kv[j] = Ks[kc * 65 + tx + 16 * j];
#pragma unroll
                for (int i = 0; i < 4; i++)
#pragma unroll
                    for (int j = 0; j < 4; j++) s[i][j] += qv[i] * kv[j];
            }
        }

        __syncthreads();   // ensure previous tile's Ps reads are done
#pragma unroll
        for (int i = 0; i < 4; i++)
#pragma unroll
            for (int j = 0; j < 4; j++) {
                const float sv = s[i][j];
                Ps[(ty * 4 + i) * 65 + tx + 16 * j] = sv / (1.0f + fabsf(sv));
            }

#pragma unroll
        for (int dc = 0; dc < 4; dc++) {
            __syncthreads();  // Ps visible (dc=0) + Vs reuse protection
#pragma unroll
            for (int i = 0; i < 16; i++) {
                const int e = i * 256 + t;
                const int m = e >> 6;
                const int c = e & 63;
                Vs[m * 65 + c] = pvb[(m0 + m) * DD + dc * 64 + c];
            }
            __syncthreads();

#pragma unroll 4
            for (int m = 0; m < 64; m++) {
                const float p = Ps[r * 65 + m];
                if (dc == 0 && q == 0) ds += p * state_s[m];
#pragma unroll
                for (int j = 0; j < 16; j++)
                    o[dc * 16 + j] += p * Vs[m * 65 + q + 4 * j];
            }
        }
    }

    // write delta_val
#pragma unroll
    for (int dc = 0; dc < 4; dc++)
#pragma unroll
        for (int j = 0; j < 16; j++)
            out_dv[((size_t)b * NN + n0 + r) * DD + dc * 64 + q + 4 * j] = o[dc * 16 + j];
    // write delta_state
    if (q == 0) out_ds[b * NN + n0 + r] = ds;
}

// ---------------------------------------------------------------------------
extern "C" void kernel_launch(void* const* d_in, const int* in_sizes, int n_in,
                              void* d_out, int out_size) {
    // resolve inputs by element count (val: B*N*D, state: B*N, Wv: D*D)
    const float* val = nullptr;
    const float* state = nullptr;
    const float* Wv = nullptr;
    for (int i = 0; i < n_in; i++) {
        if (in_sizes[i] == BB * NN * DD) val = (const float*)d_in[i];
        else if (in_sizes[i] == BB * NN) state = (const float*)d_in[i];
        else if (in_sizes[i] == DD * DD) Wv = (const float*)d_in[i];
    }

    float* out    = (float*)d_out;
    float* out_ds = out;             // [B, N]
    float* out_dv = out + BB * NN;   // [B, N, D]

    proj_kernel<<<BB * NN / 64, 256>>>(val, Wv);

    const size_t smem = (size_t)(256 * 65 + 32 * 65 + 64 * 65 + 64 * 65 + 64) * sizeof(float);
    cudaFuncSetAttribute(prop_kernel, cudaFuncAttributeMaxDynamicSharedMemorySize, (int)smem);
    prop_kernel<<<BB * (NN / 64), 256, smem>>>(val, state, out_ds, out_dv);
}